// round 8
// baseline (speedup 1.0000x reference)
#include <cuda_runtime.h>
#include <math.h>
#include <stdint.h>

#define SEQ    1024
#define DMODEL 1024
#define NQK    32
#define DQK    32
#define NOV    2048
#define BATCH  2
#define VKV    16
#define KVLEN  (SEQ + VKV)   /* 1040 */
#define RATIO  (NOV / NQK)   /* 64 */
#define FULLM  0xFFFFFFFFu

// ---------------- scratch (static device globals; no allocation) ----------------
__device__ float g_q   [(size_t)BATCH * NQK * SEQ   * DQK];   // tf32-rounded, pre-scaled 1/sqrt(32)
__device__ float g_kext[(size_t)BATCH * NQK * KVLEN * DQK];   // tf32-rounded
__device__ float g_vext[(size_t)BATCH * KVLEN * NOV];         // tf32-rounded
__device__ float g_z   [(size_t)BATCH * SEQ * NOV];
__device__ float g_sin [SEQ * 16];
__device__ float g_cos [SEQ * 16];

// ---------------- tf32 mma helpers ----------------
__device__ __forceinline__ uint32_t f2tf(float x) {
    uint32_t y;
    asm("cvt.rna.tf32.f32 %0, %1;" : "=r"(y) : "f"(x));
    return y;
}
__device__ __forceinline__ float tf32r(float x) { return __uint_as_float(f2tf(x)); }

__device__ __forceinline__ void mma8(float4& d, const uint32_t* a, const uint32_t* b) {
    asm volatile(
        "mma.sync.aligned.m16n8k8.row.col.f32.tf32.tf32.f32 "
        "{%0,%1,%2,%3}, {%4,%5,%6,%7}, {%8,%9}, {%0,%1,%2,%3};\n"
        : "+f"(d.x), "+f"(d.y), "+f"(d.z), "+f"(d.w)
        : "r"(a[0]), "r"(a[1]), "r"(a[2]), "r"(a[3]), "r"(b[0]), "r"(b[1]));
}

__device__ __forceinline__ void cp_async16(uint32_t dst_smem, const void* src, int src_bytes) {
    asm volatile("cp.async.cg.shared.global [%0], [%1], 16, %2;"
                 :: "r"(dst_smem), "l"(src), "r"(src_bytes));
}

// ---------------- rotary table ----------------
__global__ void rot_init_kernel() {
    int i = blockIdx.x * blockDim.x + threadIdx.x;
    if (i >= SEQ * 16) return;
    int pos = i >> 4, jm = i & 15;
    float freq = powf(10000.0f, (float)jm * (1.0f / 16.0f));
    float ang = (float)pos / freq;
    g_sin[i] = sinf(ang);
    g_cos[i] = cosf(ang);
}

// ---------------- append virtual k/v (tf32-rounded) ----------------
__global__ void copy_virtual_kernel(const float* __restrict__ vk,
                                    const float* __restrict__ vv)
{
    int i = blockIdx.x * blockDim.x + threadIdx.x;
    if (i < BATCH * NQK * VKV * DQK) {
        int d  = i & 31;
        int tt = (i >> 5) & 15;
        int h  = (i >> 9) & 31;
        int b  = i >> 14;
        g_kext[(((size_t)b * NQK + h) * KVLEN + SEQ + tt) * DQK + d] =
            tf32r(vk[((size_t)tt * NQK + h) * DQK + d]);
    }
    if (i < BATCH * VKV * NOV) {
        int n  = i & 2047;
        int tt = (i >> 11) & 15;
        int b  = i >> 15;
        g_vext[((size_t)b * KVLEN + SEQ + tt) * NOV + n] = tf32r(vv[(size_t)tt * NOV + n]);
    }
}

// ---------------- fused QKV projection GEMM (tf32 mma, pipelined) ----------------
// Q/K regions: B smem [k=32][n=128] pitch 136 (uint4 STS, conflict-free).
// V region:    B smem [n=128][k=32] pitch 36 (as before).
__global__ void __launch_bounds__(256) qkv_gemm_kernel(
    const float* __restrict__ resid, const float* __restrict__ Wq,
    const float* __restrict__ Wk, const float* __restrict__ Wv,
    const float* __restrict__ bq, const float* __restrict__ bk,
    const float* __restrict__ bv)
{
    extern __shared__ uint32_t dsm[];            // 73728 B
    uint32_t* As0 = dsm;                         // [2][128*36]
    uint32_t* Bs0 = dsm + 2 * 128 * 36;          // [2][4608]
    float (*Cs)[132] = (float(*)[132])dsm;       // aliases (used after mainloop)

    int nt = blockIdx.x;
    int n0 = nt * 128;
    int r0 = blockIdx.y * 128;
    int region = (nt < 8) ? 0 : (nt < 16) ? 1 : 2;
    const float* Wqk = (region == 0) ? Wq : Wk;
    int cb = (region == 0) ? n0 : n0 - 1024;
    int hbase = cb >> 5;
    const float* Bv = Wv + (size_t)(n0 - 2048) * DMODEL;

    int t = threadIdx.x, w = t >> 5, lane = t & 31;
    int g = lane >> 2, tg = lane & 3;
    int wm = w >> 1, wn = w & 1;

    float4 acc[2][8];
    #pragma unroll
    for (int i = 0; i < 2; i++)
        #pragma unroll
        for (int j = 0; j < 8; j++) acc[i][j] = make_float4(0.f, 0.f, 0.f, 0.f);

    float4 ra[4], rb[4];

    #pragma unroll
    for (int i = 0; i < 4; i++) {
        int idx = t + i * 256;
        int row = idx >> 3, kq = (idx & 7) << 2;
        ra[i] = *(const float4*)(resid + (size_t)(r0 + row) * DMODEL + kq);
    }
    if (region < 2) {
        #pragma unroll
        for (int i = 0; i < 4; i++) {
            int idx = t + i * 256;
            int h = idx >> 8, kk = (idx >> 3) & 31, d4 = (idx & 7) << 2;
            rb[i] = *(const float4*)(Wqk + (size_t)(hbase + h) * DMODEL * DQK
                                     + (size_t)kk * DQK + d4);
        }
    } else {
        #pragma unroll
        for (int i = 0; i < 4; i++) {
            int idx = t + i * 256;
            int row = idx >> 3, kq = (idx & 7) << 2;
            rb[i] = *(const float4*)(Bv + (size_t)row * DMODEL + kq);
        }
    }

    for (int kt = 0; kt < 32; kt++) {
        int buf = kt & 1;
        uint32_t* A = As0 + buf * (128 * 36);
        uint32_t* B = Bs0 + buf * 4608;

        #pragma unroll
        for (int i = 0; i < 4; i++) {
            int idx = t + i * 256;
            int row = idx >> 3, kq = (idx & 7) << 2;
            *(uint4*)&A[row * 36 + kq] =
                make_uint4(f2tf(ra[i].x), f2tf(ra[i].y), f2tf(ra[i].z), f2tf(ra[i].w));
        }
        if (region < 2) {
            // [k][n] pitch 136: thread holds W[h][kk][d4..d4+3] = B[kk][h*32+d4..+3]
            #pragma unroll
            for (int i = 0; i < 4; i++) {
                int idx = t + i * 256;
                int h = idx >> 8, kk = (idx >> 3) & 31, d4 = (idx & 7) << 2;
                *(uint4*)&B[kk * 136 + h * 32 + d4] =
                    make_uint4(f2tf(rb[i].x), f2tf(rb[i].y), f2tf(rb[i].z), f2tf(rb[i].w));
            }
        } else {
            #pragma unroll
            for (int i = 0; i < 4; i++) {
                int idx = t + i * 256;
                int row = idx >> 3, kq = (idx & 7) << 2;
                *(uint4*)&B[row * 36 + kq] =
                    make_uint4(f2tf(rb[i].x), f2tf(rb[i].y), f2tf(rb[i].z), f2tf(rb[i].w));
            }
        }
        __syncthreads();

        if (kt < 31) {
            int k0 = (kt + 1) * 32;
            #pragma unroll
            for (int i = 0; i < 4; i++) {
                int idx = t + i * 256;
                int row = idx >> 3, kq = (idx & 7) << 2;
                ra[i] = *(const float4*)(resid + (size_t)(r0 + row) * DMODEL + k0 + kq);
            }
            if (region < 2) {
                #pragma unroll
                for (int i = 0; i < 4; i++) {
                    int idx = t + i * 256;
                    int h = idx >> 8, kk = (idx >> 3) & 31, d4 = (idx & 7) << 2;
                    rb[i] = *(const float4*)(Wqk + (size_t)(hbase + h) * DMODEL * DQK
                                             + (size_t)(k0 + kk) * DQK + d4);
                }
            } else {
                #pragma unroll
                for (int i = 0; i < 4; i++) {
                    int idx = t + i * 256;
                    int row = idx >> 3, kq = (idx & 7) << 2;
                    rb[i] = *(const float4*)(Bv + (size_t)row * DMODEL + k0 + kq);
                }
            }
        }

        if (region < 2) {
            #pragma unroll
            for (int ks = 0; ks < 32; ks += 8) {
                uint32_t af[2][4];
                #pragma unroll
                for (int i = 0; i < 2; i++) {
                    int rm = wm * 32 + i * 16;
                    af[i][0] = A[(rm + g    ) * 36 + ks + tg];
                    af[i][1] = A[(rm + g + 8) * 36 + ks + tg];
                    af[i][2] = A[(rm + g    ) * 36 + ks + tg + 4];
                    af[i][3] = A[(rm + g + 8) * 36 + ks + tg + 4];
                }
                #pragma unroll
                for (int j = 0; j < 8; j++) {
                    int cn = wn * 64 + j * 8 + g;
                    uint32_t bf[2] = { B[(ks + tg) * 136 + cn], B[(ks + tg + 4) * 136 + cn] };
                    mma8(acc[0][j], af[0], bf);
                    mma8(acc[1][j], af[1], bf);
                }
            }
        } else {
            #pragma unroll
            for (int ks = 0; ks < 32; ks += 8) {
                uint32_t af[2][4];
                #pragma unroll
                for (int i = 0; i < 2; i++) {
                    int rm = wm * 32 + i * 16;
                    af[i][0] = A[(rm + g    ) * 36 + ks + tg];
                    af[i][1] = A[(rm + g + 8) * 36 + ks + tg];
                    af[i][2] = A[(rm + g    ) * 36 + ks + tg + 4];
                    af[i][3] = A[(rm + g + 8) * 36 + ks + tg + 4];
                }
                #pragma unroll
                for (int j = 0; j < 8; j++) {
                    int cn = wn * 64 + j * 8 + g;
                    uint32_t bf[2] = { B[cn * 36 + ks + tg], B[cn * 36 + ks + tg + 4] };
                    mma8(acc[0][j], af[0], bf);
                    mma8(acc[1][j], af[1], bf);
                }
            }
        }
    }

    if (region == 2) {
        int nv0 = n0 - 2048;
        #pragma unroll
        for (int i = 0; i < 2; i++) {
            int row0 = r0 + wm * 32 + i * 16 + g;
            #pragma unroll
            for (int j = 0; j < 8; j++) {
                int n = nv0 + wn * 64 + j * 8 + tg * 2;
                float2 bvv = *(const float2*)(bv + n);
                int b1 = row0 >> 10, s1 = row0 & 1023;
                *(float2*)&g_vext[((size_t)b1 * KVLEN + s1) * NOV + n] =
                    make_float2(tf32r(acc[i][j].x + bvv.x), tf32r(acc[i][j].y + bvv.y));
                int r2 = row0 + 8;
                int b2 = r2 >> 10, s2 = r2 & 1023;
                *(float2*)&g_vext[((size_t)b2 * KVLEN + s2) * NOV + n] =
                    make_float2(tf32r(acc[i][j].z + bvv.x), tf32r(acc[i][j].w + bvv.y));
            }
        }
    } else {
        __syncthreads();
        const float* bias = (region == 0) ? bq : bk;
        #pragma unroll
        for (int i = 0; i < 2; i++) {
            int rr = wm * 32 + i * 16 + g;
            #pragma unroll
            for (int j = 0; j < 8; j++) {
                int c = wn * 64 + j * 8 + tg * 2;
                float b0 = bias[cb + c];
                float b1 = bias[cb + c + 1];
                Cs[rr    ][c    ] = acc[i][j].x + b0;
                Cs[rr    ][c + 1] = acc[i][j].y + b1;
                Cs[rr + 8][c    ] = acc[i][j].z + b0;
                Cs[rr + 8][c + 1] = acc[i][j].w + b1;
            }
        }
        __syncthreads();

        const float invscale = 0.17677669529663687f;
        float sc = (region == 0) ? invscale : 1.f;
        #pragma unroll
        for (int p = 0; p < 2; p++) {
            int idx = t + p * 256;
            int r = idx >> 2, hh = idx & 3;
            int grow = r0 + r;
            int bb = grow >> 10, pos = grow & 1023;
            int h = hbase + hh;
            const float* base = &Cs[r][hh * 32];
            float* dst = (region == 0)
                ? g_q    + (((size_t)bb * NQK + h) * SEQ   + pos) * DQK
                : g_kext + (((size_t)bb * NQK + h) * KVLEN + pos) * DQK;
            #pragma unroll
            for (int c = 0; c < 32; c++) {
                float val  = base[c];
                float flip = (c < 16) ? -base[c + 16] : base[c - 16];
                int jm = c & 15;
                float sn = g_sin[pos * 16 + jm];
                float cs = g_cos[pos * 16 + jm];
                dst[c] = tf32r((val * cs + flip * sn) * sc);
            }
        }
    }
}

// ---------------- attention: tf32 mma flash, cp.async double-buffered, shuffle-P ----------------
__global__ void __launch_bounds__(256, 2) attn_mma_kernel()
{
    extern __shared__ uint32_t smem[];
    uint32_t* Kb0 = smem;                  // 2 * 2304 words
    uint32_t* Vb0 = smem + 2 * 64 * 36;    // 2 * 4608 words

    int qt = 7 - blockIdx.x;
    int h = blockIdx.y, b = blockIdx.z;
    int i0 = qt * 128;
    int t = threadIdx.x, w = t >> 5, lane = t & 31;
    int g = lane >> 2, tg = lane & 3;

    const float* kbp = g_kext + ((size_t)b * NQK + h) * KVLEN * DQK;
    const float* vbp = g_vext + (size_t)b * KVLEN * NOV + h * RATIO;

    uint32_t qf[4][4];
    {
        const float* qbase = g_q + (((size_t)b * NQK + h) * SEQ + i0 + w * 16) * DQK;
        #pragma unroll
        for (int kb = 0; kb < 4; kb++) {
            qf[kb][0] = f2tf(qbase[(size_t)g       * DQK + kb * 8 + tg]);
            qf[kb][1] = f2tf(qbase[(size_t)(g + 8) * DQK + kb * 8 + tg]);
            qf[kb][2] = f2tf(qbase[(size_t)g       * DQK + kb * 8 + tg + 4]);
            qf[kb][3] = f2tf(qbase[(size_t)(g + 8) * DQK + kb * 8 + tg + 4]);
        }
    }

    float m_lo = -INFINITY, m_hi = -INFINITY, l_lo = 0.f, l_hi = 0.f;
    float4 z[8];
    #pragma unroll
    for (int j = 0; j < 8; j++) z[j] = make_float4(0.f, 0.f, 0.f, 0.f);

    int row_lo = i0 + w * 16 + g;
    int row_hi = row_lo + 8;
    int warp_min_row = i0 + w * 16;

    int jlim = i0 + 128 + VKV;
    if (jlim > KVLEN) jlim = KVLEN;
    int nch = (jlim + 63) >> 6;

    auto issue = [&](int ch) {
        int kv0 = ch << 6;
        uint32_t* K = Kb0 + (ch & 1) * 2304;
        uint32_t* V = Vb0 + (ch & 1) * 4608;
        #pragma unroll
        for (int i = 0; i < 2; i++) {
            int idx = t + i * 256;
            int row = idx >> 3, c4 = (idx & 7) << 2;
            int gj = kv0 + row;
            int cg2 = gj < KVLEN ? gj : KVLEN - 1;
            uint32_t dst = (uint32_t)__cvta_generic_to_shared(&K[row * 36 + c4]);
            cp_async16(dst, kbp + (size_t)cg2 * DQK + c4, gj < KVLEN ? 16 : 0);
        }
        #pragma unroll
        for (int i = 0; i < 4; i++) {
            int idx = t + i * 256;
            int row = idx >> 4, c4 = (idx & 15) << 2;
            int gj = kv0 + row;
            int cg2 = gj < KVLEN ? gj : KVLEN - 1;
            uint32_t dst = (uint32_t)__cvta_generic_to_shared(&V[row * 72 + c4]);
            cp_async16(dst, vbp + (size_t)cg2 * NOV + c4, gj < KVLEN ? 16 : 0);
        }
        asm volatile("cp.async.commit_group;" ::: "memory");
    };

    issue(0);

    for (int ch = 0; ch < nch; ch++) {
        int kv0 = ch << 6;
        if (ch + 1 < nch) {
            issue(ch + 1);
            asm volatile("cp.async.wait_group 1;" ::: "memory");
        } else {
            asm volatile("cp.async.wait_group 0;" ::: "memory");
        }
        __syncthreads();

        uint32_t* K = Kb0 + (ch & 1) * 2304;
        uint32_t* V = Vb0 + (ch & 1) * 4608;

        float4 s[8];
        #pragma unroll
        for (int j = 0; j < 8; j++) s[j] = make_float4(0.f, 0.f, 0.f, 0.f);
        #pragma unroll
        for (int ks = 0; ks < 4; ks++) {
            #pragma unroll
            for (int j = 0; j < 8; j++) {
                int cn = j * 8 + g;
                uint32_t bf[2] = { K[cn * 36 + ks * 8 + tg], K[cn * 36 + ks * 8 + tg + 4] };
                mma8(s[j], qf[ks], bf);
            }
        }

        // mask only on warp-boundary chunks (warp-uniform branch)
        if (kv0 + 63 > warp_min_row + VKV || kv0 + 63 >= KVLEN) {
            #pragma unroll
            for (int j = 0; j < 8; j++) {
                int c0 = kv0 + j * 8 + 2 * tg;
                int c1 = c0 + 1;
                s[j].x = (c0 <= row_lo + VKV && c0 < KVLEN) ? s[j].x : -INFINITY;
                s[j].y = (c1 <= row_lo + VKV && c1 < KVLEN) ? s[j].y : -INFINITY;
                s[j].z = (c0 <= row_hi + VKV && c0 < KVLEN) ? s[j].z : -INFINITY;
                s[j].w = (c1 <= row_hi + VKV && c1 < KVLEN) ? s[j].w : -INFINITY;
            }
        }

        float mx_lo = -INFINITY, mx_hi = -INFINITY;
        #pragma unroll
        for (int j = 0; j < 8; j++) {
            mx_lo = fmaxf(mx_lo, fmaxf(s[j].x, s[j].y));
            mx_hi = fmaxf(mx_hi, fmaxf(s[j].z, s[j].w));
        }
        mx_lo = fmaxf(mx_lo, __shfl_xor_sync(FULLM, mx_lo, 1));
        mx_lo = fmaxf(mx_lo, __shfl_xor_sync(FULLM, mx_lo, 2));
        mx_hi = fmaxf(mx_hi, __shfl_xor_sync(FULLM, mx_hi, 1));
        mx_hi = fmaxf(mx_hi, __shfl_xor_sync(FULLM, mx_hi, 2));
        float mn_lo = fmaxf(m_lo, mx_lo);
        float mn_hi = fmaxf(m_hi, mx_hi);
        float corr_lo = __expf(m_lo - mn_lo);
        float corr_hi = __expf(m_hi - mn_hi);

        float ps_lo = 0.f, ps_hi = 0.f;
        #pragma unroll
        for (int j = 0; j < 8; j++) {
            s[j].x = __expf(s[j].x - mn_lo);
            s[j].y = __expf(s[j].y - mn_lo);
            s[j].z = __expf(s[j].z - mn_hi);
            s[j].w = __expf(s[j].w - mn_hi);
            ps_lo += s[j].x + s[j].y;
            ps_hi += s[j].z + s[j].w;
        }
        ps_lo += __shfl_xor_sync(FULLM, ps_lo, 1);
        ps_lo += __shfl_xor_sync(FULLM, ps_lo, 2);
        ps_hi += __shfl_xor_sync(FULLM, ps_hi, 1);
        ps_hi += __shfl_xor_sync(FULLM, ps_hi, 2);
        l_lo = l_lo * corr_lo + ps_lo;
        l_hi = l_hi * corr_hi + ps_hi;
        m_lo = mn_lo; m_hi = mn_hi;
        #pragma unroll
        for (int j = 0; j < 8; j++) {
            z[j].x *= corr_lo; z[j].y *= corr_lo;
            z[j].z *= corr_hi; z[j].w *= corr_hi;
        }

        // round P to tf32 (rna) before PV mma
        #pragma unroll
        for (int j = 0; j < 8; j++) {
            s[j].x = tf32r(s[j].x); s[j].y = tf32r(s[j].y);
            s[j].z = tf32r(s[j].z); s[j].w = tf32r(s[j].w);
        }

        int srcA = (lane & ~3) | (tg >> 1);
        int srcB = srcA | 2;
        bool odd = (tg & 1) != 0;
        #pragma unroll
        for (int ks = 0; ks < 8; ks++) {
            float xl  = __shfl_sync(FULLM, s[ks].x, srcA);
            float yl  = __shfl_sync(FULLM, s[ks].y, srcA);
            float xh  = __shfl_sync(FULLM, s[ks].z, srcA);
            float yh  = __shfl_sync(FULLM, s[ks].w, srcA);
            float xl2 = __shfl_sync(FULLM, s[ks].x, srcB);
            float yl2 = __shfl_sync(FULLM, s[ks].y, srcB);
            float xh2 = __shfl_sync(FULLM, s[ks].z, srcB);
            float yh2 = __shfl_sync(FULLM, s[ks].w, srcB);
            uint32_t af[4];
            af[0] = __float_as_uint(odd ? yl  : xl );
            af[1] = __float_as_uint(odd ? yh  : xh );
            af[2] = __float_as_uint(odd ? yl2 : xl2);
            af[3] = __float_as_uint(odd ? yh2 : xh2);
            #pragma unroll
            for (int j = 0; j < 8; j++) {
                int cn = j * 8 + g;
                uint32_t bf[2] = { V[(ks * 8 + tg) * 72 + cn], V[(ks * 8 + tg + 4) * 72 + cn] };
                mma8(z[j], af, bf);
            }
        }
        __syncthreads();
    }

    float li_lo = 1.f / l_lo;
    float li_hi = 1.f / l_hi;
    float* zlo = g_z + ((size_t)b * SEQ + row_lo) * NOV + h * RATIO;
    float* zhi = g_z + ((size_t)b * SEQ + row_hi) * NOV + h * RATIO;
    #pragma unroll
    for (int j = 0; j < 8; j++) {
        int col = j * 8 + 2 * tg;
        *(float2*)&zlo[col] = make_float2(z[j].x * li_lo, z[j].y * li_lo);
        *(float2*)&zhi[col] = make_float2(z[j].z * li_hi, z[j].w * li_hi);
    }
}

// ---------------- output GEMM (tf32 mma, NN, pipelined): BM=64, BN=128, grid 8x32 ----------------
__global__ void __launch_bounds__(256) out_gemm_kernel(
    const float* __restrict__ Wo, float* __restrict__ out)
{
    extern __shared__ uint32_t dsm[];
    uint32_t* As0 = dsm;                  // [2][64*36]
    uint32_t* Bs0 = dsm + 2 * 64 * 36;    // [2][32*136]

    int n0 = blockIdx.x * 128, r0 = blockIdx.y * 64;
    int t = threadIdx.x;
    int w = t >> 5, lane = t & 31;
    int g = lane >> 2, tg = lane & 3;
    int wm = w >> 1, wn = w & 1;

    float4 acc[8];
    #pragma unroll
    for (int j = 0; j < 8; j++) acc[j] = make_float4(0.f, 0.f, 0.f, 0.f);

    float4 ra[2], rb[4];
    #pragma unroll
    for (int i = 0; i < 2; i++) {
        int idx = t + i * 256;
        int row = idx >> 3, kq = (idx & 7) << 2;
        ra[i] = *(const float4*)(g_z + (size_t)(r0 + row) * NOV + kq);
    }
    #pragma unroll
    for (int i = 0; i < 4; i++) {
        int idx = t + i * 256;
        int kk = idx >> 5, nq = (idx & 31) << 2;
        rb[i] = *(const float4*)(Wo + (size_t)kk * DMODEL + n0 + nq);
    }

    for (int kt = 0; kt < 64; kt++) {
        int buf = kt & 1;
        uint32_t* A = As0 + buf * (64 * 36);
        uint32_t* B = Bs0 + buf * (32 * 136);

        #pragma unroll
        for (int i = 0; i < 2; i++) {
            int idx = t + i * 256;
            int row = idx >> 3, kq = (idx & 7) << 2;
            *(uint4*)&A[row * 36 + kq] =
                make_uint4(f2tf(ra[i].x), f2tf(ra[i].y), f2tf(ra[i].z), f2tf(ra[i].w));
        }
        #pragma unroll
        for (int i = 0; i < 4; i++) {
            int idx = t + i * 256;
            int kk = idx >> 5, nq = (idx & 31) << 2;
            *(uint4*)&B[kk * 136 + nq] =
                make_uint4(f2tf(rb[i].x), f2tf(rb[i].y), f2tf(rb[i].z), f2tf(rb[i].w));
        }
        __syncthreads();

        if (kt < 63) {
            int k0 = (kt + 1) * 32;
            #pragma unroll
            for (int i = 0; i < 2; i++) {
                int idx = t + i * 256;
                int row = idx >> 3, kq = (idx & 7) << 2;
                ra[i] = *(const float4*)(g_z + (size_t)(r0 + row) * NOV + k0 + kq);
            }
            #pragma unroll
            for (int i = 0; i < 4; i++) {
                int idx = t + i * 256;
                int kk = idx >> 5, nq = (idx & 31) << 2;
                rb[i] = *(const float4*)(Wo + (size_t)(k0 + kk) * DMODEL + n0 + nq);
            }
        }

        #pragma unroll
        for (int ks = 0; ks < 32; ks += 8) {
            uint32_t af[4];
            int rm = wm * 16;
            af[0] = A[(rm + g    ) * 36 + ks + tg];
            af[1] = A[(rm + g + 8) * 36 + ks + tg];
            af[2] = A[(rm + g    ) * 36 + ks + tg + 4];
            af[3] = A[(rm + g + 8) * 36 + ks + tg + 4];
            #pragma unroll
            for (int j = 0; j < 8; j++) {
                int cn = wn * 64 + j * 8 + g;
                uint32_t bf[2] = { B[(ks + tg) * 136 + cn], B[(ks + tg + 4) * 136 + cn] };
                mma8(acc[j], af, bf);
            }
        }
    }

    int row0 = r0 + wm * 16 + g;
    #pragma unroll
    for (int j = 0; j < 8; j++) {
        int n = n0 + wn * 64 + j * 8 + tg * 2;
        *(float2*)&out[(size_t)row0 * DMODEL + n] = make_float2(acc[j].x, acc[j].y);
        *(float2*)&out[(size_t)(row0 + 8) * DMODEL + n] = make_float2(acc[j].z, acc[j].w);
    }
}

// ---------------- launch ----------------
extern "C" void kernel_launch(void* const* d_in, const int* in_sizes, int n_in,
                              void* d_out, int out_size)
{
    const float* resid = (const float*)d_in[0];
    const float* Wq    = (const float*)d_in[1];
    const float* Wk    = (const float*)d_in[2];
    const float* Wv    = (const float*)d_in[3];
    const float* Wo    = (const float*)d_in[4];
    const float* bq    = (const float*)d_in[5];
    const float* bk    = (const float*)d_in[6];
    const float* bv    = (const float*)d_in[7];
    const float* vk    = (const float*)d_in[8];
    const float* vv    = (const float*)d_in[9];
    float* out = (float*)d_out;

    const int ATTN_SMEM = (2 * 64 * 36 + 2 * 64 * 72) * 4;     // 55296
    const int QKV_SMEM  = (2 * 128 * 36 + 2 * 4608) * 4;       // 73728
    const int OUT_SMEM  = (2 * 64 * 36 + 2 * 32 * 136) * 4;    // 53248
    static int smem_set = 0;
    if (!smem_set) {
        cudaFuncSetAttribute(attn_mma_kernel,
                             cudaFuncAttributeMaxDynamicSharedMemorySize, ATTN_SMEM);
        cudaFuncSetAttribute(qkv_gemm_kernel,
                             cudaFuncAttributeMaxDynamicSharedMemorySize, QKV_SMEM);
        cudaFuncSetAttribute(out_gemm_kernel,
                             cudaFuncAttributeMaxDynamicSharedMemorySize, OUT_SMEM);
        smem_set = 1;
    }

    rot_init_kernel<<<64, 256>>>();
    copy_virtual_kernel<<<256, 256>>>(vk, vv);
    qkv_gemm_kernel<<<dim3(32, 16), 256, QKV_SMEM>>>(resid, Wq, Wk, Wv, bq, bk, bv);
    attn_mma_kernel<<<dim3(8, 32, 2), 256, ATTN_SMEM>>>();
    out_gemm_kernel<<<dim3(8, 32), 256, OUT_SMEM>>>(Wo, out);
}

// round 9
// speedup vs baseline: 1.4149x; 1.4149x over previous
#include <cuda_runtime.h>
#include <cuda_fp16.h>
#include <math.h>
#include <stdint.h>

#define SEQ    1024
#define DMODEL 1024
#define NQK    32
#define DQK    32
#define NOV    2048
#define BATCH  2
#define VKV    16
#define KVLEN  (SEQ + VKV)   /* 1040 */
#define KVPAD  1088          /* padded kv pitch for g_vh */
#define RATIO  (NOV / NQK)   /* 64 */
#define FULLM  0xFFFFFFFFu

// ---------------- scratch (static device globals; no allocation) ----------------
__device__ __half g_qh[(size_t)BATCH * NQK * SEQ   * DQK];   // [b][h][s][d], pre-scaled 1/sqrt(32)
__device__ __half g_kh[(size_t)BATCH * NQK * KVLEN * DQK];   // [b][h][kv][d]
__device__ __half g_vh[(size_t)BATCH * NOV * KVPAD];         // [b][n][kv]  (TRANSPOSED, padded)
__device__ float  g_z [(size_t)BATCH * SEQ * NOV];           // [bs][n]  f32
__device__ float  g_sin[SEQ * 16];
__device__ float  g_cos[SEQ * 16];

// ---------------- helpers ----------------
__device__ __forceinline__ uint32_t f2tf(float x) {
    uint32_t y;
    asm("cvt.rna.tf32.f32 %0, %1;" : "=r"(y) : "f"(x));
    return y;
}
__device__ __forceinline__ uint32_t packh2(float lo, float hi) {
    __half2 h = __floats2half2_rn(lo, hi);
    return *(uint32_t*)&h;
}
// tf32 m16n8k8 (used by out_gemm only)
__device__ __forceinline__ void mma8(float4& d, const uint32_t* a, const uint32_t* b) {
    asm volatile(
        "mma.sync.aligned.m16n8k8.row.col.f32.tf32.tf32.f32 "
        "{%0,%1,%2,%3}, {%4,%5,%6,%7}, {%8,%9}, {%0,%1,%2,%3};\n"
        : "+f"(d.x), "+f"(d.y), "+f"(d.z), "+f"(d.w)
        : "r"(a[0]), "r"(a[1]), "r"(a[2]), "r"(a[3]), "r"(b[0]), "r"(b[1]));
}
// fp16 m16n8k16, f32 accumulate
__device__ __forceinline__ void mma16(float4& d, const uint32_t* a, const uint32_t* b) {
    asm volatile(
        "mma.sync.aligned.m16n8k16.row.col.f32.f16.f16.f32 "
        "{%0,%1,%2,%3}, {%4,%5,%6,%7}, {%8,%9}, {%0,%1,%2,%3};\n"
        : "+f"(d.x), "+f"(d.y), "+f"(d.z), "+f"(d.w)
        : "r"(a[0]), "r"(a[1]), "r"(a[2]), "r"(a[3]), "r"(b[0]), "r"(b[1]));
}
__device__ __forceinline__ void cp_async16(uint32_t dst_smem, const void* src, int src_bytes) {
    asm volatile("cp.async.cg.shared.global [%0], [%1], 16, %2;"
                 :: "r"(dst_smem), "l"(src), "r"(src_bytes));
}

// ---------------- rotary table ----------------
__global__ void rot_init_kernel() {
    int i = blockIdx.x * blockDim.x + threadIdx.x;
    if (i >= SEQ * 16) return;
    int pos = i >> 4, jm = i & 15;
    float freq = powf(10000.0f, (float)jm * (1.0f / 16.0f));
    float ang = (float)pos / freq;
    g_sin[i] = sinf(ang);
    g_cos[i] = cosf(ang);
}

// ---------------- append virtual k/v + zero V padding ----------------
__global__ void copy_virtual_kernel(const float* __restrict__ vk,
                                    const float* __restrict__ vv)
{
    int i = blockIdx.x * blockDim.x + threadIdx.x;
    if (i < BATCH * NQK * VKV * DQK) {   // vk -> g_kh (no rotary on virtuals)
        int d  = i & 31;
        int tt = (i >> 5) & 15;
        int h  = (i >> 9) & 31;
        int b  = i >> 14;
        g_kh[(((size_t)b * NQK + h) * KVLEN + SEQ + tt) * DQK + d] =
            __float2half(vk[((size_t)tt * NQK + h) * DQK + d]);
    }
    if (i < BATCH * NOV * 64) {          // g_vh cols 1024..1087 (virtual + zero pad)
        int c = 1024 + (i & 63);
        int n = (i >> 6) & 2047;
        int b = i >> 17;
        float val = (c < KVLEN) ? vv[(size_t)(c - SEQ) * NOV + n] : 0.f;
        g_vh[((size_t)b * NOV + n) * KVPAD + c] = __float2half(val);
    }
}

// ---------------- fused QKV projection GEMM (fp16 mma, pipelined) ----------------
// n-tiles 0..7 -> Q, 8..15 -> K, 16..31 -> V. BM=128, BN=128, BK=32.
// A/B smem: half [128][40] (20-word pitch, conflict-free frags), double buffered.
__global__ void __launch_bounds__(256) qkv_gemm_kernel(
    const float* __restrict__ resid, const float* __restrict__ Wq,
    const float* __restrict__ Wk, const float* __restrict__ Wv,
    const float* __restrict__ bq, const float* __restrict__ bk,
    const float* __restrict__ bv)
{
    extern __shared__ uint32_t dsm[];            // 67584 B (epilogue staging needs most)
    uint32_t* As0 = dsm;                         // [2][128*20] words (half data)
    uint32_t* Bs0 = dsm + 2 * 128 * 20;          // [2][128*20]
    float (*Cs)[132] = (float(*)[132])dsm;       // f32 stage alias (Q/K epilogue)
    __half* Ch = (__half*)dsm;                   // half stage alias (V transpose epilogue)

    int nt = blockIdx.x;
    int n0 = nt * 128;
    int r0 = blockIdx.y * 128;
    int region = (nt < 8) ? 0 : (nt < 16) ? 1 : 2;
    const float* Wqk = (region == 0) ? Wq : Wk;
    int cb = (region == 0) ? n0 : n0 - 1024;
    int hbase = cb >> 5;
    const float* Bv = Wv + (size_t)(n0 - 2048) * DMODEL;

    int t = threadIdx.x, w = t >> 5, lane = t & 31;
    int g = lane >> 2, tg = lane & 3;
    int wm = w >> 1, wn = w & 1;

    float4 acc[2][8];
    #pragma unroll
    for (int i = 0; i < 2; i++)
        #pragma unroll
        for (int j = 0; j < 8; j++) acc[i][j] = make_float4(0.f, 0.f, 0.f, 0.f);

    float4 ra[4];
    float  rbs[16];

    // ---- prefetch chunk 0 ----
    #pragma unroll
    for (int i = 0; i < 4; i++) {
        int idx = t + i * 256;
        int row = idx >> 3, k4 = (idx & 7) << 2;
        ra[i] = *(const float4*)(resid + (size_t)(r0 + row) * DMODEL + k4);
    }
    if (region < 2) {
        #pragma unroll
        for (int p = 0; p < 8; p++) {
            int idx = t + p * 256;
            int n = idx & 127, c = idx >> 7;
            int hl = n >> 5, d = n & 31;
            const float* src = Wqk + (size_t)(hbase + hl) * DMODEL * DQK
                               + (size_t)(2 * c) * DQK + d;
            rbs[2 * p]     = src[0];
            rbs[2 * p + 1] = src[DQK];
        }
    } else {
        #pragma unroll
        for (int i = 0; i < 4; i++) {
            int idx = t + i * 256;
            int row = idx >> 3, k4 = (idx & 7) << 2;
            float4 v = *(const float4*)(Bv + (size_t)row * DMODEL + k4);
            rbs[4 * i] = v.x; rbs[4 * i + 1] = v.y; rbs[4 * i + 2] = v.z; rbs[4 * i + 3] = v.w;
        }
    }

    for (int kt = 0; kt < 32; kt++) {
        int buf = kt & 1;
        uint32_t* A = As0 + buf * (128 * 20);
        uint32_t* B = Bs0 + buf * (128 * 20);

        // ---- STS current chunk (pack f32 pairs -> half2) ----
        #pragma unroll
        for (int i = 0; i < 4; i++) {
            int idx = t + i * 256;
            int row = idx >> 3, k4 = (idx & 7) << 2;
            *(uint2*)&A[row * 20 + (k4 >> 1)] =
                make_uint2(packh2(ra[i].x, ra[i].y), packh2(ra[i].z, ra[i].w));
        }
        if (region < 2) {
            #pragma unroll
            for (int p = 0; p < 8; p++) {
                int idx = t + p * 256;
                int n = idx & 127, c = idx >> 7;
                B[n * 20 + c] = packh2(rbs[2 * p], rbs[2 * p + 1]);
            }
        } else {
            #pragma unroll
            for (int i = 0; i < 4; i++) {
                int idx = t + i * 256;
                int row = idx >> 3, k4 = (idx & 7) << 2;
                *(uint2*)&B[row * 20 + (k4 >> 1)] =
                    make_uint2(packh2(rbs[4 * i], rbs[4 * i + 1]),
                               packh2(rbs[4 * i + 2], rbs[4 * i + 3]));
            }
        }
        __syncthreads();

        // ---- prefetch next chunk ----
        if (kt < 31) {
            int k0 = (kt + 1) * 32;
            #pragma unroll
            for (int i = 0; i < 4; i++) {
                int idx = t + i * 256;
                int row = idx >> 3, k4 = (idx & 7) << 2;
                ra[i] = *(const float4*)(resid + (size_t)(r0 + row) * DMODEL + k0 + k4);
            }
            if (region < 2) {
                #pragma unroll
                for (int p = 0; p < 8; p++) {
                    int idx = t + p * 256;
                    int n = idx & 127, c = idx >> 7;
                    int hl = n >> 5, d = n & 31;
                    const float* src = Wqk + (size_t)(hbase + hl) * DMODEL * DQK
                                       + (size_t)(k0 + 2 * c) * DQK + d;
                    rbs[2 * p]     = src[0];
                    rbs[2 * p + 1] = src[DQK];
                }
            } else {
                #pragma unroll
                for (int i = 0; i < 4; i++) {
                    int idx = t + i * 256;
                    int row = idx >> 3, k4 = (idx & 7) << 2;
                    float4 v = *(const float4*)(Bv + (size_t)row * DMODEL + k0 + k4);
                    rbs[4 * i] = v.x; rbs[4 * i + 1] = v.y;
                    rbs[4 * i + 2] = v.z; rbs[4 * i + 3] = v.w;
                }
            }
        }

        // ---- MMA (fp16 m16n8k16): 2 k-blocks ----
        #pragma unroll
        for (int kb = 0; kb < 2; kb++) {
            uint32_t af[2][4];
            #pragma unroll
            for (int i = 0; i < 2; i++) {
                int rm = wm * 32 + i * 16;
                af[i][0] = A[(rm + g    ) * 20 + 8 * kb + tg];
                af[i][1] = A[(rm + g + 8) * 20 + 8 * kb + tg];
                af[i][2] = A[(rm + g    ) * 20 + 8 * kb + 4 + tg];
                af[i][3] = A[(rm + g + 8) * 20 + 8 * kb + 4 + tg];
            }
            #pragma unroll
            for (int j = 0; j < 8; j++) {
                int cn = wn * 64 + j * 8 + g;
                uint32_t bf[2] = { B[cn * 20 + 8 * kb + tg], B[cn * 20 + 8 * kb + 4 + tg] };
                mma16(acc[0][j], af[0], bf);
                mma16(acc[1][j], af[1], bf);
            }
        }
    }

    if (region == 2) {
        // ---- V epilogue: bias + stage transposed in smem, then coalesced STG ----
        __syncthreads();
        int nv0 = n0 - 2048;
        #pragma unroll
        for (int i = 0; i < 2; i++) {
            int rl = wm * 32 + i * 16 + g;
            #pragma unroll
            for (int j = 0; j < 8; j++) {
                int n = wn * 64 + j * 8 + tg * 2;
                float2 bvv = *(const float2*)(bv + nv0 + n);
                Ch[(size_t)n       * 136 + rl    ] = __float2half(acc[i][j].x + bvv.x);
                Ch[(size_t)(n + 1) * 136 + rl    ] = __float2half(acc[i][j].y + bvv.y);
                Ch[(size_t)n       * 136 + rl + 8] = __float2half(acc[i][j].z + bvv.x);
                Ch[(size_t)(n + 1) * 136 + rl + 8] = __float2half(acc[i][j].w + bvv.y);
            }
        }
        __syncthreads();
        int b = r0 >> 10, s0 = r0 & 1023;
        #pragma unroll
        for (int p = 0; p < 8; p++) {
            int idx = t + p * 256;
            int n = idx >> 4, c8 = (idx & 15) * 8;
            uint4 v = *(uint4*)&Ch[(size_t)n * 136 + c8];
            *(uint4*)&g_vh[((size_t)b * NOV + nv0 + n) * KVPAD + s0 + c8] = v;
        }
    } else {
        // ---- Q/K epilogue: bias stage + rotary scatter (half) ----
        __syncthreads();
        const float* bias = (region == 0) ? bq : bk;
        #pragma unroll
        for (int i = 0; i < 2; i++) {
            int rr = wm * 32 + i * 16 + g;
            #pragma unroll
            for (int j = 0; j < 8; j++) {
                int c = wn * 64 + j * 8 + tg * 2;
                float b0 = bias[cb + c];
                float b1 = bias[cb + c + 1];
                Cs[rr    ][c    ] = acc[i][j].x + b0;
                Cs[rr    ][c + 1] = acc[i][j].y + b1;
                Cs[rr + 8][c    ] = acc[i][j].z + b0;
                Cs[rr + 8][c + 1] = acc[i][j].w + b1;
            }
        }
        __syncthreads();

        const float invscale = 0.17677669529663687f;   // 1/sqrt(32)
        float sc = (region == 0) ? invscale : 1.f;
        #pragma unroll
        for (int p = 0; p < 2; p++) {
            int idx = t + p * 256;
            int r = idx >> 2, hh = idx & 3;
            int grow = r0 + r;
            int bb = grow >> 10, pos = grow & 1023;
            int h = hbase + hh;
            const float* base = &Cs[r][hh * 32];
            __half* dst = (region == 0)
                ? g_qh + (((size_t)bb * NQK + h) * SEQ   + pos) * DQK
                : g_kh + (((size_t)bb * NQK + h) * KVLEN + pos) * DQK;
            #pragma unroll
            for (int c = 0; c < 32; c++) {
                float val  = base[c];
                float flip = (c < 16) ? -base[c + 16] : base[c - 16];
                int jm = c & 15;
                float sn = g_sin[pos * 16 + jm];
                float cs = g_cos[pos * 16 + jm];
                dst[c] = __float2half((val * cs + flip * sn) * sc);
            }
        }
    }
}

// ---------------- attention: fp16 mma flash, cp.async double-buffered, zero-shuffle P ----
// grid (8, 32, 2), block 256, 2 CTAs/SM.
// smem: K[2][64][40]h (10240B) + V[2][64][72]h (18432B) = 28672 B.
__global__ void __launch_bounds__(256, 2) attn_mma_kernel()
{
    extern __shared__ uint32_t smem[];
    uint32_t* Kb0 = smem;                  // per buffer 64*20 = 1280 words
    uint32_t* Vb0 = smem + 2 * 1280;       // per buffer 64*36 = 2304 words

    int qt = 7 - blockIdx.x;               // big tiles first
    int h = blockIdx.y, b = blockIdx.z;
    int i0 = qt * 128;
    int t = threadIdx.x, w = t >> 5, lane = t & 31;
    int g = lane >> 2, tg = lane & 3;

    const __half* kbp = g_kh + ((size_t)b * NQK + h) * KVLEN * DQK;
    const __half* vbp = g_vh + ((size_t)b * NOV + h * RATIO) * KVPAD;

    // Q fragments (half2 words, 2 k16-blocks)
    uint32_t qf[2][4];
    {
        const __half* qb = g_qh + (((size_t)b * NQK + h) * SEQ + i0 + w * 16) * DQK;
        #pragma unroll
        for (int kb = 0; kb < 2; kb++) {
            qf[kb][0] = *(const uint32_t*)(qb + (size_t)g       * DQK + kb * 16 + 2 * tg);
            qf[kb][1] = *(const uint32_t*)(qb + (size_t)(g + 8) * DQK + kb * 16 + 2 * tg);
            qf[kb][2] = *(const uint32_t*)(qb + (size_t)g       * DQK + kb * 16 + 8 + 2 * tg);
            qf[kb][3] = *(const uint32_t*)(qb + (size_t)(g + 8) * DQK + kb * 16 + 8 + 2 * tg);
        }
    }

    float m_lo = -INFINITY, m_hi = -INFINITY, l_lo = 0.f, l_hi = 0.f;
    float4 z[8];
    #pragma unroll
    for (int j = 0; j < 8; j++) z[j] = make_float4(0.f, 0.f, 0.f, 0.f);

    int row_lo = i0 + w * 16 + g;
    int row_hi = row_lo + 8;
    int warp_min_row = i0 + w * 16;

    int jlim = i0 + 128 + VKV;
    if (jlim > KVLEN) jlim = KVLEN;
    int nch = (jlim + 63) >> 6;

    auto issue = [&](int ch) {
        int kv0 = ch << 6;
        uint32_t* K = Kb0 + (ch & 1) * 1280;
        uint32_t* V = Vb0 + (ch & 1) * 2304;
        {   // K chunk: 64 rows x 64B -> 256 x 16B (1 per thread)
            int row = t >> 2, seg = t & 3;
            int gj = kv0 + row;
            int cg2 = gj < KVLEN ? gj : KVLEN - 1;
            uint32_t dst = (uint32_t)__cvta_generic_to_shared(&K[row * 20 + seg * 4]);
            cp_async16(dst, kbp + (size_t)cg2 * DQK + seg * 8, gj < KVLEN ? 16 : 0);
        }
        #pragma unroll
        for (int i = 0; i < 2; i++) {   // V chunk: 64 n-rows x 128B -> 512 x 16B
            int idx = t + i * 256;
            int row = idx >> 3, seg = idx & 7;
            uint32_t dst = (uint32_t)__cvta_generic_to_shared(&V[row * 36 + seg * 4]);
            cp_async16(dst, vbp + (size_t)row * KVPAD + kv0 + seg * 8, 16);
        }
        asm volatile("cp.async.commit_group;" ::: "memory");
    };

    issue(0);

    for (int ch = 0; ch < nch; ch++) {
        int kv0 = ch << 6;
        if (ch + 1 < nch) {
            issue(ch + 1);
            asm volatile("cp.async.wait_group 1;" ::: "memory");
        } else {
            asm volatile("cp.async.wait_group 0;" ::: "memory");
        }
        __syncthreads();

        uint32_t* K = Kb0 + (ch & 1) * 1280;
        uint32_t* V = Vb0 + (ch & 1) * 2304;

        // S = Q K^T  (2 k16-blocks x 8 n-blocks = 16 mma)
        float4 s[8];
        #pragma unroll
        for (int j = 0; j < 8; j++) s[j] = make_float4(0.f, 0.f, 0.f, 0.f);
        #pragma unroll
        for (int kb = 0; kb < 2; kb++) {
            #pragma unroll
            for (int j = 0; j < 8; j++) {
                int cn = j * 8 + g;
                uint32_t bf[2] = { K[cn * 20 + 8 * kb + tg], K[cn * 20 + 8 * kb + 4 + tg] };
                mma16(s[j], qf[kb], bf);
            }
        }

        // mask only on warp-boundary chunks
        if (kv0 + 63 > warp_min_row + VKV || kv0 + 63 >= KVLEN) {
            #pragma unroll
            for (int j = 0; j < 8; j++) {
                int c0 = kv0 + j * 8 + 2 * tg;
                int c1 = c0 + 1;
                s[j].x = (c0 <= row_lo + VKV && c0 < KVLEN) ? s[j].x : -INFINITY;
                s[j].y = (c1 <= row_lo + VKV && c1 < KVLEN) ? s[j].y : -INFINITY;
                s[j].z = (c0 <= row_hi + VKV && c0 < KVLEN) ? s[j].z : -INFINITY;
                s[j].w = (c1 <= row_hi + VKV && c1 < KVLEN) ? s[j].w : -INFINITY;
            }
        }

        // online softmax
        float mx_lo = -INFINITY, mx_hi = -INFINITY;
        #pragma unroll
        for (int j = 0; j < 8; j++) {
            mx_lo = fmaxf(mx_lo, fmaxf(s[j].x, s[j].y));
            mx_hi = fmaxf(mx_hi, fmaxf(s[j].z, s[j].w));
        }
        mx_lo = fmaxf(mx_lo, __shfl_xor_sync(FULLM, mx_lo, 1));
        mx_lo = fmaxf(mx_lo, __shfl_xor_sync(FULLM, mx_lo, 2));
        mx_hi = fmaxf(mx_hi, __shfl_xor_sync(FULLM, mx_hi, 1));
        mx_hi = fmaxf(mx_hi, __shfl_xor_sync(FULLM, mx_hi, 2));
        float mn_lo = fmaxf(m_lo, mx_lo);
        float mn_hi = fmaxf(m_hi, mx_hi);
        float corr_lo = __expf(m_lo - mn_lo);
        float corr_hi = __expf(m_hi - mn_hi);

        float ps_lo = 0.f, ps_hi = 0.f;
        #pragma unroll
        for (int j = 0; j < 8; j++) {
            s[j].x = __expf(s[j].x - mn_lo);
            s[j].y = __expf(s[j].y - mn_lo);
            s[j].z = __expf(s[j].z - mn_hi);
            s[j].w = __expf(s[j].w - mn_hi);
            ps_lo += s[j].x + s[j].y;
            ps_hi += s[j].z + s[j].w;
        }
        ps_lo += __shfl_xor_sync(FULLM, ps_lo, 1);
        ps_lo += __shfl_xor_sync(FULLM, ps_lo, 2);
        ps_hi += __shfl_xor_sync(FULLM, ps_hi, 1);
        ps_hi += __shfl_xor_sync(FULLM, ps_hi, 2);
        l_lo = l_lo * corr_lo + ps_lo;
        l_hi = l_hi * corr_hi + ps_hi;
        m_lo = mn_lo; m_hi = mn_hi;
        #pragma unroll
        for (int j = 0; j < 8; j++) {
            z[j].x *= corr_lo; z[j].y *= corr_lo;
            z[j].z *= corr_hi; z[j].w *= corr_hi;
        }

        // Z += P V : P A-fragments are direct half2 packs of S C-fragments (no shuffles)
        #pragma unroll
        for (int kb = 0; kb < 4; kb++) {
            uint32_t af[4];
            af[0] = packh2(s[2 * kb].x,     s[2 * kb].y);
            af[1] = packh2(s[2 * kb].z,     s[2 * kb].w);
            af[2] = packh2(s[2 * kb + 1].x, s[2 * kb + 1].y);
            af[3] = packh2(s[2 * kb + 1].z, s[2 * kb + 1].w);
            #pragma unroll
            for (int j = 0; j < 8; j++) {
                int cn = j * 8 + g;
                uint32_t bf[2] = { V[cn * 36 + 8 * kb + tg], V[cn * 36 + 8 * kb + 4 + tg] };
                mma16(z[j], af, bf);
            }
        }
        __syncthreads();
    }

    float li_lo = 1.f / l_lo;
    float li_hi = 1.f / l_hi;
    float* zlo = g_z + ((size_t)b * SEQ + row_lo) * NOV + h * RATIO;
    float* zhi = g_z + ((size_t)b * SEQ + row_hi) * NOV + h * RATIO;
    #pragma unroll
    for (int j = 0; j < 8; j++) {
        int col = j * 8 + 2 * tg;
        *(float2*)&zlo[col] = make_float2(z[j].x * li_lo, z[j].y * li_lo);
        *(float2*)&zhi[col] = make_float2(z[j].z * li_hi, z[j].w * li_hi);
    }
}

// ---------------- output GEMM (tf32 mma, NN, pipelined): BM=128, BN=128 (R6 version) -----
__global__ void __launch_bounds__(256) out_gemm_kernel(
    const float* __restrict__ Wo, float* __restrict__ out)
{
    extern __shared__ uint32_t dsm[];
    uint32_t* As0 = dsm;                  // [2][128][36]
    uint32_t* Bs0 = dsm + 2 * 128 * 36;   // [2][32][132]

    int n0 = blockIdx.x * 128, r0 = blockIdx.y * 128;
    int t = threadIdx.x;
    int w = t >> 5, lane = t & 31;
    int g = lane >> 2, tg = lane & 3;
    int wm = w >> 1, wn = w & 1;

    float4 acc[2][8];
    #pragma unroll
    for (int i = 0; i < 2; i++)
        #pragma unroll
        for (int j = 0; j < 8; j++) acc[i][j] = make_float4(0.f, 0.f, 0.f, 0.f);

    float4 ra[4], rb[4];
    #pragma unroll
    for (int i = 0; i < 4; i++) {
        int idx = t + i * 256;
        int row = idx >> 3, kq = (idx & 7) << 2;
        ra[i] = *(const float4*)(g_z + (size_t)(r0 + row) * NOV + kq);
    }
    #pragma unroll
    for (int i = 0; i < 4; i++) {
        int idx = t + i * 256;
        int kk = idx >> 5, nq = (idx & 31) << 2;
        rb[i] = *(const float4*)(Wo + (size_t)kk * DMODEL + n0 + nq);
    }

    for (int kt = 0; kt < 64; kt++) {
        int buf = kt & 1;
        uint32_t* A = As0 + buf * (128 * 36);
        uint32_t* B = Bs0 + buf * (32 * 132);

        #pragma unroll
        for (int i = 0; i < 4; i++) {
            int idx = t + i * 256;
            int row = idx >> 3, kq = (idx & 7) << 2;
            *(uint4*)&A[row * 36 + kq] =
                make_uint4(f2tf(ra[i].x), f2tf(ra[i].y), f2tf(ra[i].z), f2tf(ra[i].w));
        }
        #pragma unroll
        for (int i = 0; i < 4; i++) {
            int idx = t + i * 256;
            int kk = idx >> 5, nq = (idx & 31) << 2;
            *(uint4*)&B[kk * 132 + nq] =
                make_uint4(f2tf(rb[i].x), f2tf(rb[i].y), f2tf(rb[i].z), f2tf(rb[i].w));
        }
        __syncthreads();

        if (kt < 63) {
            int k0 = (kt + 1) * 32;
            #pragma unroll
            for (int i = 0; i < 4; i++) {
                int idx = t + i * 256;
                int row = idx >> 3, kq = (idx & 7) << 2;
                ra[i] = *(const float4*)(g_z + (size_t)(r0 + row) * NOV + k0 + kq);
            }
            #pragma unroll
            for (int i = 0; i < 4; i++) {
                int idx = t + i * 256;
                int kk = idx >> 5, nq = (idx & 31) << 2;
                rb[i] = *(const float4*)(Wo + (size_t)(k0 + kk) * DMODEL + n0 + nq);
            }
        }

        #pragma unroll
        for (int ks = 0; ks < 32; ks += 8) {
            uint32_t af[2][4];
            #pragma unroll
            for (int i = 0; i < 2; i++) {
                int rm = wm * 32 + i * 16;
                af[i][0] = A[(rm + g    ) * 36 + ks + tg];
                af[i][1] = A[(rm + g + 8) * 36 + ks + tg];
                af[i][2] = A[(rm + g    ) * 36 + ks + tg + 4];
                af[i][3] = A[(rm + g + 8) * 36 + ks + tg + 4];
            }
            #pragma unroll
            for (int j = 0; j < 8; j++) {
                int cn = wn * 64 + j * 8 + g;
                uint32_t bf[2] = { B[(ks + tg) * 132 + cn], B[(ks + tg + 4) * 132 + cn] };
                mma8(acc[0][j], af[0], bf);
                mma8(acc[1][j], af[1], bf);
            }
        }
    }

    #pragma unroll
    for (int i = 0; i < 2; i++) {
        int row0 = r0 + wm * 32 + i * 16 + g;
        #pragma unroll
        for (int j = 0; j < 8; j++) {
            int n = n0 + wn * 64 + j * 8 + tg * 2;
            *(float2*)&out[(size_t)row0 * DMODEL + n] = make_float2(acc[i][j].x, acc[i][j].y);
            *(float2*)&out[(size_t)(row0 + 8) * DMODEL + n] = make_float2(acc[i][j].z, acc[i][j].w);
        }
    }
}

// ---------------- launch ----------------
extern "C" void kernel_launch(void* const* d_in, const int* in_sizes, int n_in,
                              void* d_out, int out_size)
{
    const float* resid = (const float*)d_in[0];
    const float* Wq    = (const float*)d_in[1];
    const float* Wk    = (const float*)d_in[2];
    const float* Wv    = (const float*)d_in[3];
    const float* Wo    = (const float*)d_in[4];
    const float* bq    = (const float*)d_in[5];
    const float* bk    = (const float*)d_in[6];
    const float* bv    = (const float*)d_in[7];
    const float* vk    = (const float*)d_in[8];
    const float* vv    = (const float*)d_in[9];
    float* out = (float*)d_out;

    const int ATTN_SMEM = (2 * 1280 + 2 * 2304) * 4;           // 28672
    const int QKV_SMEM  = 128 * 132 * 4;                       // 67584 (epilogue stage)
    const int OUT_SMEM  = (2 * 128 * 36 + 2 * 32 * 132) * 4;   // 70656
    static int smem_set = 0;
    if (!smem_set) {
        cudaFuncSetAttribute(attn_mma_kernel,
                             cudaFuncAttributeMaxDynamicSharedMemorySize, ATTN_SMEM);
        cudaFuncSetAttribute(qkv_gemm_kernel,
                             cudaFuncAttributeMaxDynamicSharedMemorySize, QKV_SMEM);
        cudaFuncSetAttribute(out_gemm_kernel,
                             cudaFuncAttributeMaxDynamicSharedMemorySize, OUT_SMEM);
        smem_set = 1;
    }

    rot_init_kernel<<<64, 256>>>();
    copy_virtual_kernel<<<1024, 256>>>(vk, vv);
    qkv_gemm_kernel<<<dim3(32, 16), 256, QKV_SMEM>>>(resid, Wq, Wk, Wv, bq, bk, bv);
    attn_mma_kernel<<<dim3(8, 32, 2), 256, ATTN_SMEM>>>();
    out_gemm_kernel<<<dim3(8, 16), 256, OUT_SMEM>>>(Wo, out);
}

// round 10
// speedup vs baseline: 1.6486x; 1.1652x over previous
#include <cuda_runtime.h>
#include <cuda_fp16.h>
#include <math.h>
#include <stdint.h>

#define SEQ    1024
#define DMODEL 1024
#define NQK    32
#define DQK    32
#define NOV    2048
#define BATCH  2
#define VKV    16
#define KVLEN  (SEQ + VKV)   /* 1040 */
#define KVPAD  1088          /* padded kv pitch for g_vh */
#define RATIO  (NOV / NQK)   /* 64 */
#define FULLM  0xFFFFFFFFu

// ---------------- scratch (static device globals; no allocation) ----------------
__device__ __half g_qh[(size_t)BATCH * NQK * SEQ   * DQK];   // [b][h][s][d], pre-scaled 1/sqrt(32)
__device__ __half g_kh[(size_t)BATCH * NQK * KVLEN * DQK];   // [b][h][kv][d]
__device__ __half g_vh[(size_t)BATCH * NOV * KVPAD];         // [b][n][kv]  (TRANSPOSED, padded)
__device__ __half g_zh[(size_t)BATCH * SEQ * NOV];           // [bs][n]  half
__device__ float  g_sin[SEQ * 16];
__device__ float  g_cos[SEQ * 16];

// ---------------- helpers ----------------
__device__ __forceinline__ uint32_t packh2(float lo, float hi) {
    __half2 h = __floats2half2_rn(lo, hi);
    return *(uint32_t*)&h;
}
// fp16 m16n8k16, f32 accumulate
__device__ __forceinline__ void mma16(float4& d, const uint32_t* a, const uint32_t* b) {
    asm volatile(
        "mma.sync.aligned.m16n8k16.row.col.f32.f16.f16.f32 "
        "{%0,%1,%2,%3}, {%4,%5,%6,%7}, {%8,%9}, {%0,%1,%2,%3};\n"
        : "+f"(d.x), "+f"(d.y), "+f"(d.z), "+f"(d.w)
        : "r"(a[0]), "r"(a[1]), "r"(a[2]), "r"(a[3]), "r"(b[0]), "r"(b[1]));
}
__device__ __forceinline__ void cp_async16(uint32_t dst_smem, const void* src, int src_bytes) {
    asm volatile("cp.async.cg.shared.global [%0], [%1], 16, %2;"
                 :: "r"(dst_smem), "l"(src), "r"(src_bytes));
}

// ---------------- setup: rotary table + virtual k/v + V padding ----------------
__global__ void setup_kernel(const float* __restrict__ vk, const float* __restrict__ vv) {
    int i = blockIdx.x * blockDim.x + threadIdx.x;
    if (i < SEQ * 16) {
        int pos = i >> 4, jm = i & 15;
        float freq = powf(10000.0f, (float)jm * (1.0f / 16.0f));
        float ang = (float)pos / freq;
        g_sin[i] = sinf(ang);
        g_cos[i] = cosf(ang);
    }
    if (i < BATCH * NQK * VKV * DQK) {   // vk -> g_kh (no rotary on virtuals)
        int d  = i & 31;
        int tt = (i >> 5) & 15;
        int h  = (i >> 9) & 31;
        int b  = i >> 14;
        g_kh[(((size_t)b * NQK + h) * KVLEN + SEQ + tt) * DQK + d] =
            __float2half(vk[((size_t)tt * NQK + h) * DQK + d]);
    }
    if (i < BATCH * NOV * 64) {          // g_vh cols 1024..1087 (virtual + zero pad)
        int c = 1024 + (i & 63);
        int n = (i >> 6) & 2047;
        int b = i >> 17;
        float val = (c < KVLEN) ? vv[(size_t)(c - SEQ) * NOV + n] : 0.f;
        g_vh[((size_t)b * NOV + n) * KVPAD + c] = __float2half(val);
    }
}

// ---------------- fused QKV projection GEMM (fp16 mma, pipelined) ----------------
// n-tiles 0..7 -> Q, 8..15 -> K, 16..31 -> V. BM=128, BN=128, BK=32.
__global__ void __launch_bounds__(256) qkv_gemm_kernel(
    const float* __restrict__ resid, const float* __restrict__ Wq,
    const float* __restrict__ Wk, const float* __restrict__ Wv,
    const float* __restrict__ bq, const float* __restrict__ bk,
    const float* __restrict__ bv)
{
    extern __shared__ uint32_t dsm[];            // 67584 B (epilogue staging needs most)
    uint32_t* As0 = dsm;                         // [2][128*20] words (half data)
    uint32_t* Bs0 = dsm + 2 * 128 * 20;          // [2][128*20]
    float (*Cs)[132] = (float(*)[132])dsm;       // f32 stage alias (Q/K epilogue)
    __half* Ch = (__half*)dsm;                   // half stage alias (V transpose epilogue)

    int nt = blockIdx.x;
    int n0 = nt * 128;
    int r0 = blockIdx.y * 128;
    int region = (nt < 8) ? 0 : (nt < 16) ? 1 : 2;
    const float* Wqk = (region == 0) ? Wq : Wk;
    int cb = (region == 0) ? n0 : n0 - 1024;
    int hbase = cb >> 5;
    const float* Bv = Wv + (size_t)(n0 - 2048) * DMODEL;

    int t = threadIdx.x, w = t >> 5, lane = t & 31;
    int g = lane >> 2, tg = lane & 3;
    int wm = w >> 1, wn = w & 1;

    float4 acc[2][8];
    #pragma unroll
    for (int i = 0; i < 2; i++)
        #pragma unroll
        for (int j = 0; j < 8; j++) acc[i][j] = make_float4(0.f, 0.f, 0.f, 0.f);

    float4 ra[4];
    float  rbs[16];

    #pragma unroll
    for (int i = 0; i < 4; i++) {
        int idx = t + i * 256;
        int row = idx >> 3, k4 = (idx & 7) << 2;
        ra[i] = *(const float4*)(resid + (size_t)(r0 + row) * DMODEL + k4);
    }
    if (region < 2) {
        #pragma unroll
        for (int p = 0; p < 8; p++) {
            int idx = t + p * 256;
            int n = idx & 127, c = idx >> 7;
            int hl = n >> 5, d = n & 31;
            const float* src = Wqk + (size_t)(hbase + hl) * DMODEL * DQK
                               + (size_t)(2 * c) * DQK + d;
            rbs[2 * p]     = src[0];
            rbs[2 * p + 1] = src[DQK];
        }
    } else {
        #pragma unroll
        for (int i = 0; i < 4; i++) {
            int idx = t + i * 256;
            int row = idx >> 3, k4 = (idx & 7) << 2;
            float4 v = *(const float4*)(Bv + (size_t)row * DMODEL + k4);
            rbs[4 * i] = v.x; rbs[4 * i + 1] = v.y; rbs[4 * i + 2] = v.z; rbs[4 * i + 3] = v.w;
        }
    }

    for (int kt = 0; kt < 32; kt++) {
        int buf = kt & 1;
        uint32_t* A = As0 + buf * (128 * 20);
        uint32_t* B = Bs0 + buf * (128 * 20);

        #pragma unroll
        for (int i = 0; i < 4; i++) {
            int idx = t + i * 256;
            int row = idx >> 3, k4 = (idx & 7) << 2;
            *(uint2*)&A[row * 20 + (k4 >> 1)] =
                make_uint2(packh2(ra[i].x, ra[i].y), packh2(ra[i].z, ra[i].w));
        }
        if (region < 2) {
            #pragma unroll
            for (int p = 0; p < 8; p++) {
                int idx = t + p * 256;
                int n = idx & 127, c = idx >> 7;
                B[n * 20 + c] = packh2(rbs[2 * p], rbs[2 * p + 1]);
            }
        } else {
            #pragma unroll
            for (int i = 0; i < 4; i++) {
                int idx = t + i * 256;
                int row = idx >> 3, k4 = (idx & 7) << 2;
                *(uint2*)&B[row * 20 + (k4 >> 1)] =
                    make_uint2(packh2(rbs[4 * i], rbs[4 * i + 1]),
                               packh2(rbs[4 * i + 2], rbs[4 * i + 3]));
            }
        }
        __syncthreads();

        if (kt < 31) {
            int k0 = (kt + 1) * 32;
            #pragma unroll
            for (int i = 0; i < 4; i++) {
                int idx = t + i * 256;
                int row = idx >> 3, k4 = (idx & 7) << 2;
                ra[i] = *(const float4*)(resid + (size_t)(r0 + row) * DMODEL + k0 + k4);
            }
            if (region < 2) {
                #pragma unroll
                for (int p = 0; p < 8; p++) {
                    int idx = t + p * 256;
                    int n = idx & 127, c = idx >> 7;
                    int hl = n >> 5, d = n & 31;
                    const float* src = Wqk + (size_t)(hbase + hl) * DMODEL * DQK
                                       + (size_t)(k0 + 2 * c) * DQK + d;
                    rbs[2 * p]     = src[0];
                    rbs[2 * p + 1] = src[DQK];
                }
            } else {
                #pragma unroll
                for (int i = 0; i < 4; i++) {
                    int idx = t + i * 256;
                    int row = idx >> 3, k4 = (idx & 7) << 2;
                    float4 v = *(const float4*)(Bv + (size_t)row * DMODEL + k0 + k4);
                    rbs[4 * i] = v.x; rbs[4 * i + 1] = v.y;
                    rbs[4 * i + 2] = v.z; rbs[4 * i + 3] = v.w;
                }
            }
        }

        #pragma unroll
        for (int kb = 0; kb < 2; kb++) {
            uint32_t af[2][4];
            #pragma unroll
            for (int i = 0; i < 2; i++) {
                int rm = wm * 32 + i * 16;
                af[i][0] = A[(rm + g    ) * 20 + 8 * kb + tg];
                af[i][1] = A[(rm + g + 8) * 20 + 8 * kb + tg];
                af[i][2] = A[(rm + g    ) * 20 + 8 * kb + 4 + tg];
                af[i][3] = A[(rm + g + 8) * 20 + 8 * kb + 4 + tg];
            }
            #pragma unroll
            for (int j = 0; j < 8; j++) {
                int cn = wn * 64 + j * 8 + g;
                uint32_t bf[2] = { B[cn * 20 + 8 * kb + tg], B[cn * 20 + 8 * kb + 4 + tg] };
                mma16(acc[0][j], af[0], bf);
                mma16(acc[1][j], af[1], bf);
            }
        }
    }

    if (region == 2) {
        __syncthreads();
        int nv0 = n0 - 2048;
        #pragma unroll
        for (int i = 0; i < 2; i++) {
            int rl = wm * 32 + i * 16 + g;
            #pragma unroll
            for (int j = 0; j < 8; j++) {
                int n = wn * 64 + j * 8 + tg * 2;
                float2 bvv = *(const float2*)(bv + nv0 + n);
                Ch[(size_t)n       * 136 + rl    ] = __float2half(acc[i][j].x + bvv.x);
                Ch[(size_t)(n + 1) * 136 + rl    ] = __float2half(acc[i][j].y + bvv.y);
                Ch[(size_t)n       * 136 + rl + 8] = __float2half(acc[i][j].z + bvv.x);
                Ch[(size_t)(n + 1) * 136 + rl + 8] = __float2half(acc[i][j].w + bvv.y);
            }
        }
        __syncthreads();
        int b = r0 >> 10, s0 = r0 & 1023;
        #pragma unroll
        for (int p = 0; p < 8; p++) {
            int idx = t + p * 256;
            int n = idx >> 4, c8 = (idx & 15) * 8;
            uint4 v = *(uint4*)&Ch[(size_t)n * 136 + c8];
            *(uint4*)&g_vh[((size_t)b * NOV + nv0 + n) * KVPAD + s0 + c8] = v;
        }
    } else {
        __syncthreads();
        const float* bias = (region == 0) ? bq : bk;
        #pragma unroll
        for (int i = 0; i < 2; i++) {
            int rr = wm * 32 + i * 16 + g;
            #pragma unroll
            for (int j = 0; j < 8; j++) {
                int c = wn * 64 + j * 8 + tg * 2;
                float b0 = bias[cb + c];
                float b1 = bias[cb + c + 1];
                Cs[rr    ][c    ] = acc[i][j].x + b0;
                Cs[rr    ][c + 1] = acc[i][j].y + b1;
                Cs[rr + 8][c    ] = acc[i][j].z + b0;
                Cs[rr + 8][c + 1] = acc[i][j].w + b1;
            }
        }
        __syncthreads();

        const float invscale = 0.17677669529663687f;   // 1/sqrt(32)
        float sc = (region == 0) ? invscale : 1.f;
        #pragma unroll
        for (int p = 0; p < 2; p++) {
            int idx = t + p * 256;
            int r = idx >> 2, hh = idx & 3;
            int grow = r0 + r;
            int bb = grow >> 10, pos = grow & 1023;
            int h = hbase + hh;
            const float* base = &Cs[r][hh * 32];
            __half* dst = (region == 0)
                ? g_qh + (((size_t)bb * NQK + h) * SEQ   + pos) * DQK
                : g_kh + (((size_t)bb * NQK + h) * KVLEN + pos) * DQK;
            #pragma unroll
            for (int c = 0; c < 32; c++) {
                float val  = base[c];
                float flip = (c < 16) ? -base[c + 16] : base[c - 16];
                int jm = c & 15;
                float sn = g_sin[pos * 16 + jm];
                float cs = g_cos[pos * 16 + jm];
                dst[c] = __float2half((val * cs + flip * sn) * sc);
            }
        }
    }
}

// ---------------- attention: fp16 mma flash, cp.async double-buffered ----------------
__global__ void __launch_bounds__(256, 2) attn_mma_kernel()
{
    extern __shared__ uint32_t smem[];
    uint32_t* Kb0 = smem;                  // per buffer 64*20 = 1280 words
    uint32_t* Vb0 = smem + 2 * 1280;       // per buffer 64*36 = 2304 words

    int qt = 7 - blockIdx.x;               // big tiles first
    int h = blockIdx.y, b = blockIdx.z;
    int i0 = qt * 128;
    int t = threadIdx.x, w = t >> 5, lane = t & 31;
    int g = lane >> 2, tg = lane & 3;

    const __half* kbp = g_kh + ((size_t)b * NQK + h) * KVLEN * DQK;
    const __half* vbp = g_vh + ((size_t)b * NOV + h * RATIO) * KVPAD;

    uint32_t qf[2][4];
    {
        const __half* qb = g_qh + (((size_t)b * NQK + h) * SEQ + i0 + w * 16) * DQK;
        #pragma unroll
        for (int kb = 0; kb < 2; kb++) {
            qf[kb][0] = *(const uint32_t*)(qb + (size_t)g       * DQK + kb * 16 + 2 * tg);
            qf[kb][1] = *(const uint32_t*)(qb + (size_t)(g + 8) * DQK + kb * 16 + 2 * tg);
            qf[kb][2] = *(const uint32_t*)(qb + (size_t)g       * DQK + kb * 16 + 8 + 2 * tg);
            qf[kb][3] = *(const uint32_t*)(qb + (size_t)(g + 8) * DQK + kb * 16 + 8 + 2 * tg);
        }
    }

    float m_lo = -INFINITY, m_hi = -INFINITY, l_lo = 0.f, l_hi = 0.f;
    float4 z[8];
    #pragma unroll
    for (int j = 0; j < 8; j++) z[j] = make_float4(0.f, 0.f, 0.f, 0.f);

    int row_lo = i0 + w * 16 + g;
    int row_hi = row_lo + 8;
    int warp_min_row = i0 + w * 16;

    int jlim = i0 + 128 + VKV;
    if (jlim > KVLEN) jlim = KVLEN;
    int nch = (jlim + 63) >> 6;

    auto issue = [&](int ch) {
        int kv0 = ch << 6;
        uint32_t* K = Kb0 + (ch & 1) * 1280;
        uint32_t* V = Vb0 + (ch & 1) * 2304;
        {
            int row = t >> 2, seg = t & 3;
            int gj = kv0 + row;
            int cg2 = gj < KVLEN ? gj : KVLEN - 1;
            uint32_t dst = (uint32_t)__cvta_generic_to_shared(&K[row * 20 + seg * 4]);
            cp_async16(dst, kbp + (size_t)cg2 * DQK + seg * 8, gj < KVLEN ? 16 : 0);
        }
        #pragma unroll
        for (int i = 0; i < 2; i++) {
            int idx = t + i * 256;
            int row = idx >> 3, seg = idx & 7;
            uint32_t dst = (uint32_t)__cvta_generic_to_shared(&V[row * 36 + seg * 4]);
            cp_async16(dst, vbp + (size_t)row * KVPAD + kv0 + seg * 8, 16);
        }
        asm volatile("cp.async.commit_group;" ::: "memory");
    };

    issue(0);

    for (int ch = 0; ch < nch; ch++) {
        int kv0 = ch << 6;
        if (ch + 1 < nch) {
            issue(ch + 1);
            asm volatile("cp.async.wait_group 1;" ::: "memory");
        } else {
            asm volatile("cp.async.wait_group 0;" ::: "memory");
        }
        __syncthreads();

        uint32_t* K = Kb0 + (ch & 1) * 1280;
        uint32_t* V = Vb0 + (ch & 1) * 2304;

        float4 s[8];
        #pragma unroll
        for (int j = 0; j < 8; j++) s[j] = make_float4(0.f, 0.f, 0.f, 0.f);
        #pragma unroll
        for (int kb = 0; kb < 2; kb++) {
            #pragma unroll
            for (int j = 0; j < 8; j++) {
                int cn = j * 8 + g;
                uint32_t bf[2] = { K[cn * 20 + 8 * kb + tg], K[cn * 20 + 8 * kb + 4 + tg] };
                mma16(s[j], qf[kb], bf);
            }
        }

        if (kv0 + 63 > warp_min_row + VKV || kv0 + 63 >= KVLEN) {
            #pragma unroll
            for (int j = 0; j < 8; j++) {
                int c0 = kv0 + j * 8 + 2 * tg;
                int c1 = c0 + 1;
                s[j].x = (c0 <= row_lo + VKV && c0 < KVLEN) ? s[j].x : -INFINITY;
                s[j].y = (c1 <= row_lo + VKV && c1 < KVLEN) ? s[j].y : -INFINITY;
                s[j].z = (c0 <= row_hi + VKV && c0 < KVLEN) ? s[j].z : -INFINITY;
                s[j].w = (c1 <= row_hi + VKV && c1 < KVLEN) ? s[j].w : -INFINITY;
            }
        }

        float mx_lo = -INFINITY, mx_hi = -INFINITY;
        #pragma unroll
        for (int j = 0; j < 8; j++) {
            mx_lo = fmaxf(mx_lo, fmaxf(s[j].x, s[j].y));
            mx_hi = fmaxf(mx_hi, fmaxf(s[j].z, s[j].w));
        }
        mx_lo = fmaxf(mx_lo, __shfl_xor_sync(FULLM, mx_lo, 1));
        mx_lo = fmaxf(mx_lo, __shfl_xor_sync(FULLM, mx_lo, 2));
        mx_hi = fmaxf(mx_hi, __shfl_xor_sync(FULLM, mx_hi, 1));
        mx_hi = fmaxf(mx_hi, __shfl_xor_sync(FULLM, mx_hi, 2));
        float mn_lo = fmaxf(m_lo, mx_lo);
        float mn_hi = fmaxf(m_hi, mx_hi);
        float corr_lo = __expf(m_lo - mn_lo);
        float corr_hi = __expf(m_hi - mn_hi);

        float ps_lo = 0.f, ps_hi = 0.f;
        #pragma unroll
        for (int j = 0; j < 8; j++) {
            s[j].x = __expf(s[j].x - mn_lo);
            s[j].y = __expf(s[j].y - mn_lo);
            s[j].z = __expf(s[j].z - mn_hi);
            s[j].w = __expf(s[j].w - mn_hi);
            ps_lo += s[j].x + s[j].y;
            ps_hi += s[j].z + s[j].w;
        }
        ps_lo += __shfl_xor_sync(FULLM, ps_lo, 1);
        ps_lo += __shfl_xor_sync(FULLM, ps_lo, 2);
        ps_hi += __shfl_xor_sync(FULLM, ps_hi, 1);
        ps_hi += __shfl_xor_sync(FULLM, ps_hi, 2);
        l_lo = l_lo * corr_lo + ps_lo;
        l_hi = l_hi * corr_hi + ps_hi;
        m_lo = mn_lo; m_hi = mn_hi;
        #pragma unroll
        for (int j = 0; j < 8; j++) {
            z[j].x *= corr_lo; z[j].y *= corr_lo;
            z[j].z *= corr_hi; z[j].w *= corr_hi;
        }

        #pragma unroll
        for (int kb = 0; kb < 4; kb++) {
            uint32_t af[4];
            af[0] = packh2(s[2 * kb].x,     s[2 * kb].y);
            af[1] = packh2(s[2 * kb].z,     s[2 * kb].w);
            af[2] = packh2(s[2 * kb + 1].x, s[2 * kb + 1].y);
            af[3] = packh2(s[2 * kb + 1].z, s[2 * kb + 1].w);
            #pragma unroll
            for (int j = 0; j < 8; j++) {
                int cn = j * 8 + g;
                uint32_t bf[2] = { V[cn * 36 + 8 * kb + tg], V[cn * 36 + 8 * kb + 4 + tg] };
                mma16(z[j], af, bf);
            }
        }
        __syncthreads();
    }

    float li_lo = 1.f / l_lo;
    float li_hi = 1.f / l_hi;
    __half* zlo = g_zh + ((size_t)b * SEQ + row_lo) * NOV + h * RATIO;
    __half* zhi = g_zh + ((size_t)b * SEQ + row_hi) * NOV + h * RATIO;
    #pragma unroll
    for (int j = 0; j < 8; j++) {
        int col = j * 8 + 2 * tg;
        *(uint32_t*)&zlo[col] = packh2(z[j].x * li_lo, z[j].y * li_lo);
        *(uint32_t*)&zhi[col] = packh2(z[j].z * li_hi, z[j].w * li_hi);
    }
}

// ---------------- output GEMM (fp16 mma, NN, pipelined): BM=128, BN=128 ----------------
// A = g_zh [2048][2048] half (direct uint4 copies). B = Wo f32 packed to half2 k-pairs.
__global__ void __launch_bounds__(256) out_gemm_kernel(
    const float* __restrict__ Wo, float* __restrict__ out)
{
    extern __shared__ uint32_t dsm[];
    uint32_t* As0 = dsm;                  // [2][128*20] words (half data)
    uint32_t* Bs0 = dsm + 2 * 128 * 20;   // [2][128*20]  ([n][k-pair] pitch 20)

    int n0 = blockIdx.x * 128, r0 = blockIdx.y * 128;
    int t = threadIdx.x;
    int w = t >> 5, lane = t & 31;
    int g = lane >> 2, tg = lane & 3;
    int wm = w >> 1, wn = w & 1;

    float4 acc[2][8];
    #pragma unroll
    for (int i = 0; i < 2; i++)
        #pragma unroll
        for (int j = 0; j < 8; j++) acc[i][j] = make_float4(0.f, 0.f, 0.f, 0.f);

    uint4 ra[2];
    float rbs[16];

    #pragma unroll
    for (int i = 0; i < 2; i++) {
        int idx = t + i * 256;
        int row = idx >> 2, seg = idx & 3;
        ra[i] = *(const uint4*)(g_zh + (size_t)(r0 + row) * NOV + seg * 8);
    }
    #pragma unroll
    for (int p = 0; p < 8; p++) {
        int idx = t + p * 256;
        int n = idx & 127, c = idx >> 7;
        rbs[2 * p]     = Wo[(size_t)(2 * c)     * DMODEL + n0 + n];
        rbs[2 * p + 1] = Wo[(size_t)(2 * c + 1) * DMODEL + n0 + n];
    }

    for (int kt = 0; kt < 64; kt++) {
        int buf = kt & 1;
        uint32_t* A = As0 + buf * (128 * 20);
        uint32_t* B = Bs0 + buf * (128 * 20);

        #pragma unroll
        for (int i = 0; i < 2; i++) {
            int idx = t + i * 256;
            int row = idx >> 2, seg = idx & 3;
            *(uint4*)&A[row * 20 + seg * 4] = ra[i];
        }
        #pragma unroll
        for (int p = 0; p < 8; p++) {
            int idx = t + p * 256;
            int n = idx & 127, c = idx >> 7;
            B[n * 20 + c] = packh2(rbs[2 * p], rbs[2 * p + 1]);
        }
        __syncthreads();

        if (kt < 63) {
            int k0 = (kt + 1) * 32;
            #pragma unroll
            for (int i = 0; i < 2; i++) {
                int idx = t + i * 256;
                int row = idx >> 2, seg = idx & 3;
                ra[i] = *(const uint4*)(g_zh + (size_t)(r0 + row) * NOV + k0 + seg * 8);
            }
            #pragma unroll
            for (int p = 0; p < 8; p++) {
                int idx = t + p * 256;
                int n = idx & 127, c = idx >> 7;
                rbs[2 * p]     = Wo[(size_t)(k0 + 2 * c)     * DMODEL + n0 + n];
                rbs[2 * p + 1] = Wo[(size_t)(k0 + 2 * c + 1) * DMODEL + n0 + n];
            }
        }

        #pragma unroll
        for (int kb = 0; kb < 2; kb++) {
            uint32_t af[2][4];
            #pragma unroll
            for (int i = 0; i < 2; i++) {
                int rm = wm * 32 + i * 16;
                af[i][0] = A[(rm + g    ) * 20 + 8 * kb + tg];
                af[i][1] = A[(rm + g + 8) * 20 + 8 * kb + tg];
                af[i][2] = A[(rm + g    ) * 20 + 8 * kb + 4 + tg];
                af[i][3] = A[(rm + g + 8) * 20 + 8 * kb + 4 + tg];
            }
            #pragma unroll
            for (int j = 0; j < 8; j++) {
                int cn = wn * 64 + j * 8 + g;
                uint32_t bf[2] = { B[cn * 20 + 8 * kb + tg], B[cn * 20 + 8 * kb + 4 + tg] };
                mma16(acc[0][j], af[0], bf);
                mma16(acc[1][j], af[1], bf);
            }
        }
    }

    #pragma unroll
    for (int i = 0; i < 2; i++) {
        int row0 = r0 + wm * 32 + i * 16 + g;
        #pragma unroll
        for (int j = 0; j < 8; j++) {
            int n = n0 + wn * 64 + j * 8 + tg * 2;
            *(float2*)&out[(size_t)row0 * DMODEL + n] = make_float2(acc[i][j].x, acc[i][j].y);
            *(float2*)&out[(size_t)(row0 + 8) * DMODEL + n] = make_float2(acc[i][j].z, acc[i][j].w);
        }
    }
}

// ---------------- launch ----------------
extern "C" void kernel_launch(void* const* d_in, const int* in_sizes, int n_in,
                              void* d_out, int out_size)
{
    const float* resid = (const float*)d_in[0];
    const float* Wq    = (const float*)d_in[1];
    const float* Wk    = (const float*)d_in[2];
    const float* Wv    = (const float*)d_in[3];
    const float* Wo    = (const float*)d_in[4];
    const float* bq    = (const float*)d_in[5];
    const float* bk    = (const float*)d_in[6];
    const float* bv    = (const float*)d_in[7];
    const float* vk    = (const float*)d_in[8];
    const float* vv    = (const float*)d_in[9];
    float* out = (float*)d_out;

    const int ATTN_SMEM = (2 * 1280 + 2 * 2304) * 4;   // 28672
    const int QKV_SMEM  = 128 * 132 * 4;               // 67584 (epilogue stage)
    const int OUT_SMEM  = (2 * 128 * 20 * 2) * 4;      // 40960
    static int smem_set = 0;
    if (!smem_set) {
        cudaFuncSetAttribute(attn_mma_kernel,
                             cudaFuncAttributeMaxDynamicSharedMemorySize, ATTN_SMEM);
        cudaFuncSetAttribute(qkv_gemm_kernel,
                             cudaFuncAttributeMaxDynamicSharedMemorySize, QKV_SMEM);
        cudaFuncSetAttribute(out_gemm_kernel,
                             cudaFuncAttributeMaxDynamicSharedMemorySize, OUT_SMEM);
        smem_set = 1;
    }

    setup_kernel<<<1024, 256>>>(vk, vv);
    qkv_gemm_kernel<<<dim3(32, 16), 256, QKV_SMEM>>>(resid, Wq, Wk, Wv, bq, bk, bv);
    attn_mma_kernel<<<dim3(8, 32, 2), 256, ATTN_SMEM>>>();
    out_gemm_kernel<<<dim3(8, 16), 256, OUT_SMEM>>>(Wo, out);
}